// round 9
// baseline (speedup 1.0000x reference)
#include <cuda_runtime.h>
#include <cstdint>

#define N_NODES_MAX 50016
#define FEAT 256
#define MULC 64

typedef unsigned long long u64t;

// ---------------- scratch (static device globals; no allocs) ----------------
// QUAD layout: [node][u][4] = {x0[u], x1[u][0], x1[u][1], x1[u][2]}
__device__ float g_xl[N_NODES_MAX * FEAT];
__device__ float g_agg[N_NODES_MAX * FEAT];
// Stage-linearized weights for fctp_dual (stage = 8 u-iters):
// i = v*64+u, s = i>>3, ui = i&7 : g_WSA[((s*4 + m)*8 + ui)*64 + w]
__device__ float g_WSA[80 * 4 * 8 * 64];
// For fctp_final (stage = 16 u-iters): s16 = i>>4, ui = i&15
// g_WSC[((s16*2 + m)*16 + ui)*64 + w]
__device__ float g_WSC[40 * 2 * 16 * 64];
// Lane-exact packed tp weights, de-interleaved
__device__ float g_tppA[32 * 32 * 4];
__device__ float g_tppB[32 * 32 * 4];

// ---------------- f32x2 packed-FMA helpers ----------------
__device__ __forceinline__ u64t pack2s(float a) {          // splat {a, a}
    u64t r;
    asm("mov.b64 %0, {%1, %1};" : "=l"(r) : "f"(a));
    return r;
}
__device__ __forceinline__ void unpack2(u64t v, float& a, float& b) {
    asm("mov.b64 {%0, %1}, %2;" : "=f"(a), "=f"(b) : "l"(v));
}
__device__ __forceinline__ void ffma2(u64t& d, u64t a, u64t b) {
    asm("fma.rn.f32x2 %0, %1, %2, %0;" : "+l"(d) : "l"(a), "l"(b));
}

__device__ __forceinline__ void red_add_v4(float* p, float4 v) {
    asm volatile("red.global.add.v4.f32 [%0], {%1,%2,%3,%4};"
                 :: "l"(p), "f"(v.x), "f"(v.y), "f"(v.z), "f"(v.w) : "memory");
}

// ---------------- cp.async helpers ----------------
__device__ __forceinline__ void cp16(uint32_t saddr, const float* g) {
    asm volatile("cp.async.cg.shared.global [%0], [%1], 16;" :: "r"(saddr), "l"(g));
}
__device__ __forceinline__ void cp_commit() {
    asm volatile("cp.async.commit_group;" ::: "memory");
}
__device__ __forceinline__ void cp_wait1() {
    asm volatile("cp.async.wait_group 1;" ::: "memory");
}

#define STAGE_F 2048   // floats per stage (8 KB)

// ---------------- weight prepack ----------------
__global__ void prepack_kernel(const float* __restrict__ si0, const float* __restrict__ si1,
                               const float* __restrict__ l10, const float* __restrict__ l11,
                               const float* __restrict__ l20, const float* __restrict__ l21) {
    int idx = blockIdx.x * blockDim.x + threadIdx.x;  // idx = u*640 + v*64 + w
    if (idx >= 64 * 10 * 64) return;
    int w = idx & 63;
    int v = (idx >> 6) % 10;
    int u = idx / 640;
    int i = v * 64 + u;
    // dual staged layout (stage = 8 u-iters)
    int s = i >> 3, ui = i & 7;
    g_WSA[((s * 4 + 0) * 8 + ui) * 64 + w] = si0[idx];
    g_WSA[((s * 4 + 1) * 8 + ui) * 64 + w] = si1[idx];
    g_WSA[((s * 4 + 2) * 8 + ui) * 64 + w] = l10[idx];
    g_WSA[((s * 4 + 3) * 8 + ui) * 64 + w] = l11[idx];
    // final staged layout (stage = 16 u-iters)
    int s16 = i >> 4, ui16 = i & 15;
    g_WSC[((s16 * 2 + 0) * 16 + ui16) * 64 + w] = l20[idx];
    g_WSC[((s16 * 2 + 1) * 16 + ui16) * 64 + w] = l21[idx];
}

__global__ void prepack_tp_kernel(const float* __restrict__ tpw) {
    int i = blockIdx.x * blockDim.x + threadIdx.x;  // i = d*32 + lane
    if (i >= 32 * 32) return;
    int d = i >> 5, lane = i & 31;
    const float* row = tpw + d * 256;
    float* a = g_tppA + i * 4;
    a[0] = row[lane];        a[1] = row[64 + lane];
    a[2] = row[128 + lane];  a[3] = row[192 + lane];
    float* b = g_tppB + i * 4;
    b[0] = row[32 + lane];   b[1] = row[96 + lane];
    b[2] = row[160 + lane];  b[3] = row[224 + lane];
}

// ---------------- zero agg ----------------
__global__ void zero_agg_kernel(int n4) {
    float4* p = (float4*)g_agg;
    float4 z = make_float4(0.f, 0.f, 0.f, 0.f);
    for (int i = blockIdx.x * blockDim.x + threadIdx.x; i < n4; i += gridDim.x * blockDim.x)
        p[i] = z;
}

// ---------------- fctp dual: s -> out_s (orig layout), xl -> g_xl (quad layout) ----------------
// 80 stages x 8 u-iters; weights cp.async triple-buffered; 2 blocks/SM.
__global__ __launch_bounds__(256, 2) void fctp_dual_kernel(
    const float* __restrict__ x, const float* __restrict__ z,
    float* __restrict__ out_s, int n)
{
    __shared__ float4 Xs[64 * 32];                    // 32 KB
    __shared__ __align__(16) float Wsm[3 * STAGE_F];  // 24 KB triple buffer
    __shared__ float zsh[32][11];

    const int t = threadIdx.x;
    const int nbase = blockIdx.x * 32;
    const int ng = t >> 4;
    const int w4 = t & 15;
    const int ln0 = ng * 2;

    const uint32_t wbase = (uint32_t)__cvta_generic_to_shared(Wsm);

    // prologue: prefetch stages 0, 1 (2048 floats each = two 16B chunks per thread)
    cp16(wbase + t * 16, g_WSA + t * 4);
    cp16(wbase + 4096 + t * 16, g_WSA + 1024 + t * 4);
    cp_commit();
    cp16(wbase + 8192 + t * 16, g_WSA + 2048 + t * 4);
    cp16(wbase + 12288 + t * 16, g_WSA + 3072 + t * 4);
    cp_commit();

    // stage X and z (overlaps with cp.async)
#pragma unroll
    for (int i = 0; i < 8; i++) {
        int f = t + i * 256;
        int u = f >> 5, ln = f & 31;
        int node = nbase + ln;
        float4 val = make_float4(0.f, 0.f, 0.f, 0.f);
        if (node < n) {
            const float* xr = x + (size_t)node * FEAT;
            val.x = xr[u];
            val.y = xr[64 + 3 * u];
            val.z = xr[64 + 3 * u + 1];
            val.w = xr[64 + 3 * u + 2];
        }
        Xs[f] = val;
    }
    for (int i = t; i < 320; i += 256) {
        int ln = i / 10, v = i % 10;
        int node = nbase + ln;
        zsh[ln][v] = (node < n) ? z[(size_t)node * 10 + v] : 0.f;
    }
    __syncthreads();

    u64t accS2[16], accL2[16];
#pragma unroll
    for (int i = 0; i < 16; i++) { accS2[i] = 0ull; accL2[i] = 0ull; }

    int b = 0;   // buffer for current stage s
    for (int s = 0; s < 80; s++) {
        cp_wait1();
        __syncthreads();

        // prefetch stage s+2 into buffer (s+2)%3
        int s2 = s + 2;
        if (s2 < 80) {
            int b2 = b + 2; if (b2 >= 3) b2 -= 3;
            uint32_t sb = wbase + (b2 * STAGE_F + t * 4) * 4;
            const float* gb = g_WSA + (size_t)s2 * STAGE_F + t * 4;
            cp16(sb, gb);
            cp16(sb + 4096, gb + 1024);
        }
        cp_commit();

        const int v = s >> 3;
        const float zr0 = zsh[ln0][v];
        const float zr1 = zsh[ln0 + 1][v];
        const ulonglong2* Wb = (const ulonglong2*)(Wsm + b * STAGE_F);
        const int ub = (s & 7) * 8;

#pragma unroll
        for (int ui = 0; ui < 8; ui++) {
            int u = ub + ui;
            float4 xq0 = Xs[u * 32 + ln0];
            float4 xq1 = Xs[u * 32 + ln0 + 1];
            ulonglong2 wsi0 = Wb[(0 * 8 + ui) * 16 + w4];
            ulonglong2 wsi1 = Wb[(1 * 8 + ui) * 16 + w4];
            ulonglong2 wl10 = Wb[(2 * 8 + ui) * 16 + w4];
            ulonglong2 wl11 = Wb[(3 * 8 + ui) * 16 + w4];

            u64t a00 = pack2s(xq0.x * zr0), a01 = pack2s(xq0.y * zr0);
            u64t a02 = pack2s(xq0.z * zr0), a03 = pack2s(xq0.w * zr0);
            u64t a10 = pack2s(xq1.x * zr1), a11 = pack2s(xq1.y * zr1);
            u64t a12 = pack2s(xq1.z * zr1), a13 = pack2s(xq1.w * zr1);

            ffma2(accS2[0],  a00, wsi0.x); ffma2(accS2[1],  a00, wsi0.y);
            ffma2(accS2[2],  a01, wsi1.x); ffma2(accS2[3],  a01, wsi1.y);
            ffma2(accS2[4],  a02, wsi1.x); ffma2(accS2[5],  a02, wsi1.y);
            ffma2(accS2[6],  a03, wsi1.x); ffma2(accS2[7],  a03, wsi1.y);
            ffma2(accS2[8],  a10, wsi0.x); ffma2(accS2[9],  a10, wsi0.y);
            ffma2(accS2[10], a11, wsi1.x); ffma2(accS2[11], a11, wsi1.y);
            ffma2(accS2[12], a12, wsi1.x); ffma2(accS2[13], a12, wsi1.y);
            ffma2(accS2[14], a13, wsi1.x); ffma2(accS2[15], a13, wsi1.y);

            ffma2(accL2[0],  a00, wl10.x); ffma2(accL2[1],  a00, wl10.y);
            ffma2(accL2[2],  a01, wl11.x); ffma2(accL2[3],  a01, wl11.y);
            ffma2(accL2[4],  a02, wl11.x); ffma2(accL2[5],  a02, wl11.y);
            ffma2(accL2[6],  a03, wl11.x); ffma2(accL2[7],  a03, wl11.y);
            ffma2(accL2[8],  a10, wl10.x); ffma2(accL2[9],  a10, wl10.y);
            ffma2(accL2[10], a11, wl11.x); ffma2(accL2[11], a11, wl11.y);
            ffma2(accL2[12], a12, wl11.x); ffma2(accL2[13], a12, wl11.y);
            ffma2(accL2[14], a13, wl11.x); ffma2(accL2[15], a13, wl11.y);
        }

        if (++b >= 3) b -= 3;
    }

    float accS[32], accL[32];
#pragma unroll
    for (int p = 0; p < 16; p++) {
        unpack2(accS2[p], accS[2 * p], accS[2 * p + 1]);
        unpack2(accL2[p], accL[2 * p], accL[2 * p + 1]);
    }

    const float sc = 0.03952847075210474f;  // 1/sqrt(640)
#pragma unroll
    for (int nn = 0; nn < 2; nn++) {
        int node = nbase + ln0 + nn;
        if (node >= n) continue;
        float* os = out_s + (size_t)node * FEAT;
        float4* ox4 = (float4*)(g_xl + (size_t)node * FEAT);
        const float* aS = accS + nn * 16;
        const float* aL = accL + nn * 16;
#pragma unroll
        for (int j = 0; j < 4; j++) {
            int w = w4 * 4 + j;
            os[w] = aS[j] * sc;
#pragma unroll
            for (int c = 1; c < 4; c++)
                os[64 + 3 * w + c - 1] = aS[c * 4 + j] * sc;
            ox4[w] = make_float4(aL[j] * sc, aL[4 + j] * sc, aL[8 + j] * sc, aL[12 + j] * sc);
        }
    }
}

// ---------------- final fctp: out += fctp(agg(quad), z, W_l2)/10 ----------------
// 40 stages x 16 u-iters; weights cp.async triple-buffered; 2 blocks/SM.
__global__ __launch_bounds__(256, 2) void fctp_final_kernel(
    const float* __restrict__ z, float* __restrict__ out, int n)
{
    __shared__ float4 Xs[64 * 32];
    __shared__ __align__(16) float Wsm[3 * STAGE_F];
    __shared__ float zsh[32][11];

    const int t = threadIdx.x;
    const int nbase = blockIdx.x * 32;
    const int ng = t >> 4;
    const int w4 = t & 15;
    const int ln0 = ng * 2;

    const uint32_t wbase = (uint32_t)__cvta_generic_to_shared(Wsm);

    cp16(wbase + t * 16, g_WSC + t * 4);
    cp16(wbase + 4096 + t * 16, g_WSC + 1024 + t * 4);
    cp_commit();
    cp16(wbase + 8192 + t * 16, g_WSC + 2048 + t * 4);
    cp16(wbase + 12288 + t * 16, g_WSC + 3072 + t * 4);
    cp_commit();

    const float4* agg4 = (const float4*)g_agg;
#pragma unroll
    for (int i = 0; i < 8; i++) {
        int f = t + i * 256;
        int u = f >> 5, ln = f & 31;
        int node = nbase + ln;
        Xs[f] = (node < n) ? agg4[(size_t)node * 64 + u]
                           : make_float4(0.f, 0.f, 0.f, 0.f);
    }
    for (int i = t; i < 320; i += 256) {
        int ln = i / 10, v = i % 10;
        int node = nbase + ln;
        zsh[ln][v] = (node < n) ? z[(size_t)node * 10 + v] : 0.f;
    }
    __syncthreads();

    u64t acc2[16];
#pragma unroll
    for (int i = 0; i < 16; i++) acc2[i] = 0ull;

    int b = 0;
    for (int s = 0; s < 40; s++) {
        cp_wait1();
        __syncthreads();

        int s2 = s + 2;
        if (s2 < 40) {
            int b2 = b + 2; if (b2 >= 3) b2 -= 3;
            uint32_t sb = wbase + (b2 * STAGE_F + t * 4) * 4;
            const float* gb = g_WSC + (size_t)s2 * STAGE_F + t * 4;
            cp16(sb, gb);
            cp16(sb + 4096, gb + 1024);
        }
        cp_commit();

        const int v = s >> 2;
        const float zr0 = zsh[ln0][v];
        const float zr1 = zsh[ln0 + 1][v];
        const ulonglong2* Wb = (const ulonglong2*)(Wsm + b * STAGE_F);
        const int ub = (s & 3) * 16;

#pragma unroll
        for (int ui = 0; ui < 16; ui++) {
            int u = ub + ui;
            float4 xq0 = Xs[u * 32 + ln0];
            float4 xq1 = Xs[u * 32 + ln0 + 1];
            ulonglong2 wl20 = Wb[(0 * 16 + ui) * 16 + w4];
            ulonglong2 wl21 = Wb[(1 * 16 + ui) * 16 + w4];

            u64t a00 = pack2s(xq0.x * zr0), a01 = pack2s(xq0.y * zr0);
            u64t a02 = pack2s(xq0.z * zr0), a03 = pack2s(xq0.w * zr0);
            u64t a10 = pack2s(xq1.x * zr1), a11 = pack2s(xq1.y * zr1);
            u64t a12 = pack2s(xq1.z * zr1), a13 = pack2s(xq1.w * zr1);

            ffma2(acc2[0],  a00, wl20.x); ffma2(acc2[1],  a00, wl20.y);
            ffma2(acc2[2],  a01, wl21.x); ffma2(acc2[3],  a01, wl21.y);
            ffma2(acc2[4],  a02, wl21.x); ffma2(acc2[5],  a02, wl21.y);
            ffma2(acc2[6],  a03, wl21.x); ffma2(acc2[7],  a03, wl21.y);
            ffma2(acc2[8],  a10, wl20.x); ffma2(acc2[9],  a10, wl20.y);
            ffma2(acc2[10], a11, wl21.x); ffma2(acc2[11], a11, wl21.y);
            ffma2(acc2[12], a12, wl21.x); ffma2(acc2[13], a12, wl21.y);
            ffma2(acc2[14], a13, wl21.x); ffma2(acc2[15], a13, wl21.y);
        }

        if (++b >= 3) b -= 3;
    }

    float acc[32];
#pragma unroll
    for (int p = 0; p < 16; p++) unpack2(acc2[p], acc[2 * p], acc[2 * p + 1]);

    const float sc = 0.03952847075210474f * 0.1f;  // (1/sqrt(640)) / 10
#pragma unroll
    for (int nn = 0; nn < 2; nn++) {
        int node = nbase + ln0 + nn;
        if (node >= n) continue;
        float* os = out + (size_t)node * FEAT;
        const float* a = acc + nn * 16;
#pragma unroll
        for (int j = 0; j < 4; j++) {
            int w = w4 * 4 + j;
            os[w] += a[j] * sc;
#pragma unroll
            for (int c = 1; c < 4; c++)
                os[64 + 3 * w + c - 1] += a[c * 4 + j] * sc;
        }
    }
}

// ---------------- edge kernel: 4 edges/warp, no smem, f32x2 GEMM ----------------
#define EPW 4
__global__ __launch_bounds__(256) void edge_kernel(
    const int* __restrict__ esrc, const int* __restrict__ edst,
    const float* __restrict__ elen, const float* __restrict__ eattr,
    int n_edges)
{
    const int warp = threadIdx.x >> 5;
    const int lane = threadIdx.x & 31;
    const int ebase = (blockIdx.x * 8 + warp) * EPW;
    if (ebase >= n_edges) return;

    float el[EPW];
    int esafe[EPW];
    bool valid[EPW];
#pragma unroll
    for (int j = 0; j < EPW; j++) {
        int e = ebase + j;
        valid[j] = (e < n_edges);
        esafe[j] = valid[j] ? e : (n_edges - 1);
        el[j] = elen[(size_t)esafe[j] * 32 + lane];
    }

    u64t acc2[EPW * 4];
#pragma unroll
    for (int i = 0; i < EPW * 4; i++) acc2[i] = 0ull;
    const ulonglong2* tpA8 = (const ulonglong2*)g_tppA;
    const ulonglong2* tpB8 = (const ulonglong2*)g_tppB;
#pragma unroll 8
    for (int d = 0; d < 32; d++) {
        ulonglong2 tA = tpA8[d * 32 + lane];
        ulonglong2 tB = tpB8[d * 32 + lane];
#pragma unroll
        for (int j = 0; j < EPW; j++) {
            u64t ed = pack2s(__shfl_sync(0xffffffffu, el[j], d));
            ffma2(acc2[j * 4 + 0], ed, tA.x);
            ffma2(acc2[j * 4 + 1], ed, tA.y);
            ffma2(acc2[j * 4 + 2], ed, tB.x);
            ffma2(acc2[j * 4 + 3], ed, tB.y);
        }
    }

    const float ISQ2 = 0.7071067811865476f;
    const float ISQ3 = 0.5773502691896258f;

#pragma unroll
    for (int j = 0; j < EPW; j++) {
        if (!valid[j]) continue;
        int e = esafe[j];
        int src = esrc[e];
        int dst = edst[e];
        float4 at = ((const float4*)eattr)[e];  // (sh0, sh1x, sh1y, sh1z)

        float wv[8];
        unpack2(acc2[j * 4 + 0], wv[0], wv[1]);
        unpack2(acc2[j * 4 + 1], wv[2], wv[3]);
        unpack2(acc2[j * 4 + 2], wv[4], wv[5]);
        unpack2(acc2[j * 4 + 3], wv[6], wv[7]);

        const float4* xr = (const float4*)(g_xl + (size_t)src * FEAT);
        float* aggp = g_agg + (size_t)dst * FEAT;
#pragma unroll
        for (int h = 0; h < 2; h++) {
            float4 xq = xr[lane + 32 * h];     // {x0, x10, x11, x12}
            float w1  = wv[h * 4 + 0];
            float w2v = wv[h * 4 + 1];
            float w3  = wv[h * 4 + 2];
            float w4v = wv[h * 4 + 3];
            float dot = xq.y * at.y + xq.z * at.z + xq.w * at.w;
            float4 o;
            o.x = ISQ2 * (w1 * xq.x * at.x + ISQ3 * w4v * dot);
            o.y = ISQ2 * (w2v * xq.x * at.y + w3 * xq.y * at.x);
            o.z = ISQ2 * (w2v * xq.x * at.z + w3 * xq.z * at.x);
            o.w = ISQ2 * (w2v * xq.x * at.w + w3 * xq.w * at.x);
            red_add_v4(aggp + (lane + 32 * h) * 4, o);
        }
    }
}

// ---------------- launch ----------------
extern "C" void kernel_launch(void* const* d_in, const int* in_sizes, int n_in,
                              void* d_out, int out_size) {
    const float* x     = (const float*)d_in[0];
    const float* z     = (const float*)d_in[1];
    const int*   esrc  = (const int*)d_in[2];
    const int*   edst  = (const int*)d_in[3];
    const float* elen  = (const float*)d_in[4];
    const float* eattr = (const float*)d_in[5];
    const float* Wsi0  = (const float*)d_in[6];
    const float* Wsi1  = (const float*)d_in[7];
    const float* Wl10  = (const float*)d_in[8];
    const float* Wl11  = (const float*)d_in[9];
    const float* Wl20  = (const float*)d_in[10];
    const float* Wl21  = (const float*)d_in[11];
    const float* tpw   = (const float*)d_in[12];
    float* out = (float*)d_out;

    const int n_nodes = in_sizes[0] / FEAT;
    const int n_edges = in_sizes[2];

    prepack_kernel<<<(64 * 10 * 64 + 255) / 256, 256>>>(Wsi0, Wsi1, Wl10, Wl11, Wl20, Wl21);
    prepack_tp_kernel<<<4, 256>>>(tpw);
    zero_agg_kernel<<<512, 256>>>(n_nodes * (FEAT / 4));

    const int nblocks = (n_nodes + 31) / 32;
    fctp_dual_kernel<<<nblocks, 256>>>(x, z, out, n_nodes);

    const int edges_per_block = 8 * EPW;
    edge_kernel<<<(n_edges + edges_per_block - 1) / edges_per_block, 256>>>(
        esrc, edst, elen, eattr, n_edges);

    fctp_final_kernel<<<nblocks, 256>>>(z, out, n_nodes);
}

// round 11
// speedup vs baseline: 1.4816x; 1.4816x over previous
#include <cuda_runtime.h>
#include <cuda_bf16.h>
#include <cstdint>

#define N_NODES_MAX 50016
#define FEAT 256
#define PLANE (N_NODES_MAX * 64)

typedef unsigned long long u64t;

// ---------------- scratch ----------------
__device__ float g_xl[4 * PLANE];             // planar: plane c, [node][u]
__device__ float g_agg[N_NODES_MAX * FEAT];   // quad layout [node][u][4]
__device__ float g_WSC[40 * 2 * 16 * 64];     // final staged weights
// Fragment-linear B weights for dual MMA:
// idx = ((s*4 + kc)*16 + nt)*32 + lane ; uint4 = {BhR0, BhR1, BlR0, BlR1}
__device__ uint4 g_WF[40 * 4 * 16 * 32];
__device__ float g_tppA[32 * 32 * 4];
__device__ float g_tppB[32 * 32 * 4];

// ---------------- helpers ----------------
__device__ __forceinline__ u64t pack2s(float a) {
    u64t r; asm("mov.b64 %0, {%1, %1};" : "=l"(r) : "f"(a)); return r;
}
__device__ __forceinline__ void unpack2(u64t v, float& a, float& b) {
    asm("mov.b64 {%0, %1}, %2;" : "=f"(a), "=f"(b) : "l"(v));
}
__device__ __forceinline__ void ffma2(u64t& d, u64t a, u64t b) {
    asm("fma.rn.f32x2 %0, %1, %2, %0;" : "+l"(d) : "l"(a), "l"(b));
}
__device__ __forceinline__ void red_add_v4(float* p, float4 v) {
    asm volatile("red.global.add.v4.f32 [%0], {%1,%2,%3,%4};"
                 :: "l"(p), "f"(v.x), "f"(v.y), "f"(v.z), "f"(v.w) : "memory");
}
__device__ __forceinline__ void cp16(uint32_t saddr, const void* g) {
    asm volatile("cp.async.cg.shared.global [%0], [%1], 16;" :: "r"(saddr), "l"(g));
}
__device__ __forceinline__ void cp_commit() { asm volatile("cp.async.commit_group;" ::: "memory"); }
__device__ __forceinline__ void cp_waitg1() { asm volatile("cp.async.wait_group 1;" ::: "memory"); }
__device__ __forceinline__ uint32_t smem_u32(const void* p) {
    uint32_t a;
    asm("{ .reg .u64 t; cvta.to.shared.u64 t, %1; cvt.u32.u64 %0, t; }" : "=r"(a) : "l"(p));
    return a;
}
// split a pair of f32 into packed bf16x2 hi and lo parts: {lo16 = e0, hi16 = e1}
__device__ __forceinline__ void split2(float e0, float e1, uint32_t& hp, uint32_t& lp) {
    asm("cvt.rn.bf16x2.f32 %0, %1, %2;" : "=r"(hp) : "f"(e1), "f"(e0));
    float h0 = __uint_as_float(hp << 16);
    float h1 = __uint_as_float(hp & 0xFFFF0000u);
    asm("cvt.rn.bf16x2.f32 %0, %1, %2;" : "=r"(lp) : "f"(e1 - h1), "f"(e0 - h0));
}

#define MMA16816(c, a, b0, b1) \
    asm volatile("mma.sync.aligned.m16n8k16.row.col.f32.bf16.bf16.f32 " \
        "{%0,%1,%2,%3}, {%4,%5,%6,%7}, {%8,%9}, {%0,%1,%2,%3};" \
        : "+f"((c)[0]), "+f"((c)[1]), "+f"((c)[2]), "+f"((c)[3]) \
        : "r"((a)[0]), "r"((a)[1]), "r"((a)[2]), "r"((a)[3]), "r"(b0), "r"(b1))

// ---------------- prepacks ----------------
__global__ void prepack_wf_kernel(const float* __restrict__ si0, const float* __restrict__ si1,
                                  const float* __restrict__ l10, const float* __restrict__ l11) {
    int idx = blockIdx.x * blockDim.x + threadIdx.x;
    if (idx >= 40 * 4 * 16 * 32) return;
    int lane = idx & 31;
    int nt = (idx >> 5) & 15;
    int kc = (idx >> 9) & 3;
    int s = idx >> 11;
    int ch = s / 10, v = s % 10;
    int gid = lane >> 2, t2 = lane & 3;
    int n = nt * 8 + gid;
    int w = n & 63;
    const float* src = (n >= 64) ? (ch == 0 ? l10 : l11) : (ch == 0 ? si0 : si1);
    int u0 = kc * 16 + t2 * 2;
    float v00 = src[((u0 + 0) * 10 + v) * 64 + w];
    float v01 = src[((u0 + 1) * 10 + v) * 64 + w];
    float v10 = src[((u0 + 8) * 10 + v) * 64 + w];
    float v11 = src[((u0 + 9) * 10 + v) * 64 + w];
    uint32_t h0, l0, h1, l1;
    split2(v00, v01, h0, l0);
    split2(v10, v11, h1, l1);
    g_WF[idx] = make_uint4(h0, h1, l0, l1);
}

__global__ void prepack_final_kernel(const float* __restrict__ l20, const float* __restrict__ l21) {
    int idx = blockIdx.x * blockDim.x + threadIdx.x;
    if (idx >= 64 * 10 * 64) return;
    int w = idx & 63;
    int v = (idx >> 6) % 10;
    int u = idx / 640;
    int i = v * 64 + u;
    int s16 = i >> 4, ui16 = i & 15;
    g_WSC[((s16 * 2 + 0) * 16 + ui16) * 64 + w] = l20[idx];
    g_WSC[((s16 * 2 + 1) * 16 + ui16) * 64 + w] = l21[idx];
}

__global__ void prepack_tp_kernel(const float* __restrict__ tpw) {
    int i = blockIdx.x * blockDim.x + threadIdx.x;
    if (i >= 32 * 32) return;
    int d = i >> 5, lane = i & 31;
    const float* row = tpw + d * 256;
    float* a = g_tppA + i * 4;
    a[0] = row[lane];        a[1] = row[64 + lane];
    a[2] = row[128 + lane];  a[3] = row[192 + lane];
    float* b = g_tppB + i * 4;
    b[0] = row[32 + lane];   b[1] = row[96 + lane];
    b[2] = row[160 + lane];  b[3] = row[224 + lane];
}

__global__ void zero_agg_kernel(int n4) {
    float4* p = (float4*)g_agg;
    float4 z = make_float4(0.f, 0.f, 0.f, 0.f);
    for (int i = blockIdx.x * blockDim.x + threadIdx.x; i < n4; i += gridDim.x * blockDim.x)
        p[i] = z;
}

// ---------------- fctp dual via mma.sync (HMMA bf16, 2-term split) ----------------
// smem: Bsm 2x32768 | xs 128x68 f32 (34816 B) | zs 1280 f32 (5120 B)
#define OFF_XS 65536
#define OFF_ZS (65536 + 34816)
#define SMEM_NEED (65536 + 34816 + 5120)

__global__ __launch_bounds__(256, 2) void fctp_dual_mma_kernel(
    const float* __restrict__ x, const float* __restrict__ z,
    float* __restrict__ out_s, int nn)
{
    extern __shared__ char sm[];
    char* Bsm = sm;
    float* xs = (float*)(sm + OFF_XS);
    float* zs = (float*)(sm + OFF_ZS);

    const int t = threadIdx.x;
    const int wid = t >> 5;
    const int lane = t & 31;
    const int gid = lane >> 2;
    const int t2 = lane & 3;
    const int warp_m = wid & 3;
    const int warp_n = wid >> 2;
    const int nbase = blockIdx.x * 128;

    const uint32_t bsm_u = smem_u32(Bsm);

    // stage z
    for (int i = t; i < 1280; i += 256) {
        int node = nbase + i / 10;
        zs[i] = (node < nn) ? z[(size_t)nbase * 10 + i] : 0.f;
    }
    // prefetch B stage 0
    {
        const uint4* gsrc = g_WF;
#pragma unroll
        for (int k = 0; k < 8; k++)
            cp16(bsm_u + t * 16 + k * 4096, gsrc + t + k * 256);
        cp_commit();
    }

    float acc[2][8][4];
#pragma unroll
    for (int a = 0; a < 2; a++)
#pragma unroll
        for (int b = 0; b < 8; b++)
#pragma unroll
            for (int c = 0; c < 4; c++) acc[a][b][c] = 0.f;

    const float sc = 0.03952847075210474f;  // 1/sqrt(640)

    for (int s = 0; s < 40; s++) {
        const int ch = s / 10;
        const int v = s % 10;
        const int buf = s & 1;

        __syncthreads();   // everyone done with stage s-1 (and prev ch's xs)

        if (v == 0) {
            // stage x slice for channel ch
            for (int i = t; i < 8192; i += 256) {
                int row = i >> 6, u = i & 63;
                int node = nbase + row;
                int col = (ch == 0) ? u : (64 + 3 * u + (ch - 1));
                xs[row * 68 + u] = (node < nn) ? x[(size_t)node * 256 + col] : 0.f;
            }
        }
        // prefetch next B stage
        if (s + 1 < 40) {
            const uint4* gsrc = g_WF + (size_t)(s + 1) * 2048;
            uint32_t dst = bsm_u + (buf ^ 1) * 32768;
#pragma unroll
            for (int k = 0; k < 8; k++)
                cp16(dst + t * 16 + k * 4096, gsrc + t + k * 256);
        }
        cp_commit();
        cp_waitg1();
        __syncthreads();   // B(s) + xs visible to all

        // hoist z per v
        float zr[2][2];
#pragma unroll
        for (int mt = 0; mt < 2; mt++) {
            int r = warp_m * 32 + mt * 16 + gid;
            zr[mt][0] = zs[r * 10 + v];
            zr[mt][1] = zs[(r + 8) * 10 + v];
        }

        char* Bbuf = Bsm + buf * 32768;

#pragma unroll 1
        for (int kc = 0; kc < 4; kc++) {
            uint32_t Ah[2][4], Al[2][4];
#pragma unroll
            for (int mt = 0; mt < 2; mt++) {
                int r0 = warp_m * 32 + mt * 16 + gid;
                int ub = kc * 16 + t2 * 2;
                float2 x00 = *(const float2*)(xs + r0 * 68 + ub);
                float2 x01 = *(const float2*)(xs + r0 * 68 + ub + 8);
                float2 x10 = *(const float2*)(xs + (r0 + 8) * 68 + ub);
                float2 x11 = *(const float2*)(xs + (r0 + 8) * 68 + ub + 8);
                float z0 = zr[mt][0], z1 = zr[mt][1];
                split2(x00.x * z0, x00.y * z0, Ah[mt][0], Al[mt][0]);
                split2(x10.x * z1, x10.y * z1, Ah[mt][1], Al[mt][1]);
                split2(x01.x * z0, x01.y * z0, Ah[mt][2], Al[mt][2]);
                split2(x11.x * z1, x11.y * z1, Ah[mt][3], Al[mt][3]);
            }
#pragma unroll
            for (int nt = 0; nt < 8; nt++) {
                uint4 B4 = *(const uint4*)(Bbuf + (((kc * 16) + warp_n * 8 + nt) * 32 + lane) * 16);
#pragma unroll
                for (int mt = 0; mt < 2; mt++) {
                    MMA16816(acc[mt][nt], Ah[mt], B4.x, B4.y);   // Ah*Bh
                    MMA16816(acc[mt][nt], Ah[mt], B4.z, B4.w);   // Ah*Bl
                    MMA16816(acc[mt][nt], Al[mt], B4.x, B4.y);   // Al*Bh
                }
            }
        }

        if (v == 9) {
            // epilogue for channel ch
#pragma unroll
            for (int mt = 0; mt < 2; mt++) {
#pragma unroll
                for (int nt = 0; nt < 8; nt++) {
                    int ntg = warp_n * 8 + nt;
                    int n0 = ntg * 8 + t2 * 2;
                    int r0 = nbase + warp_m * 32 + mt * 16 + gid;
                    int r1 = r0 + 8;
                    float c0 = acc[mt][nt][0] * sc;
                    float c1 = acc[mt][nt][1] * sc;
                    float c2 = acc[mt][nt][2] * sc;
                    float c3 = acc[mt][nt][3] * sc;
                    if (warp_n == 0) {
                        int w = n0;
                        if (ch == 0) {
                            if (r0 < nn) *(float2*)(out_s + (size_t)r0 * 256 + w) = make_float2(c0, c1);
                            if (r1 < nn) *(float2*)(out_s + (size_t)r1 * 256 + w) = make_float2(c2, c3);
                        } else {
                            int off = 64 + 3 * w + (ch - 1);
                            if (r0 < nn) {
                                out_s[(size_t)r0 * 256 + off] = c0;
                                out_s[(size_t)r0 * 256 + off + 3] = c1;
                            }
                            if (r1 < nn) {
                                out_s[(size_t)r1 * 256 + off] = c2;
                                out_s[(size_t)r1 * 256 + off + 3] = c3;
                            }
                        }
                    } else {
                        int w = n0 - 64;
                        float* xlp = g_xl + (size_t)ch * PLANE;
                        if (r0 < nn) *(float2*)(xlp + (size_t)r0 * 64 + w) = make_float2(c0, c1);
                        if (r1 < nn) *(float2*)(xlp + (size_t)r1 * 64 + w) = make_float2(c2, c3);
                    }
                    acc[mt][nt][0] = 0.f; acc[mt][nt][1] = 0.f;
                    acc[mt][nt][2] = 0.f; acc[mt][nt][3] = 0.f;
                }
            }
        }
    }
}

// ---------------- final fctp (scalar) ----------------
#define STAGE_F 2048
__global__ __launch_bounds__(256, 2) void fctp_final_kernel(
    const float* __restrict__ z, float* __restrict__ out, int n)
{
    __shared__ float4 Xs[64 * 32];
    __shared__ __align__(16) float Wsm[3 * STAGE_F];
    __shared__ float zsh[32][11];

    const int t = threadIdx.x;
    const int nbase = blockIdx.x * 32;
    const int ng = t >> 4;
    const int w4 = t & 15;
    const int ln0 = ng * 2;

    const uint32_t wbase = smem_u32(Wsm);

    cp16(wbase + t * 16, g_WSC + t * 4);
    cp16(wbase + 4096 + t * 16, g_WSC + 1024 + t * 4);
    cp_commit();
    cp16(wbase + 8192 + t * 16, g_WSC + 2048 + t * 4);
    cp16(wbase + 12288 + t * 16, g_WSC + 3072 + t * 4);
    cp_commit();

    const float4* agg4 = (const float4*)g_agg;
#pragma unroll
    for (int i = 0; i < 8; i++) {
        int f = t + i * 256;
        int u = f >> 5, ln = f & 31;
        int node = nbase + ln;
        Xs[f] = (node < n) ? agg4[(size_t)node * 64 + u]
                           : make_float4(0.f, 0.f, 0.f, 0.f);
    }
    for (int i = t; i < 320; i += 256) {
        int ln = i / 10, v = i % 10;
        int node = nbase + ln;
        zsh[ln][v] = (node < n) ? z[(size_t)node * 10 + v] : 0.f;
    }
    __syncthreads();

    u64t acc2[16];
#pragma unroll
    for (int i = 0; i < 16; i++) acc2[i] = 0ull;

    int b = 0;
    for (int s = 0; s < 40; s++) {
        cp_waitg1();
        __syncthreads();

        int s2 = s + 2;
        if (s2 < 40) {
            int b2 = b + 2; if (b2 >= 3) b2 -= 3;
            uint32_t sb = wbase + (b2 * STAGE_F + t * 4) * 4;
            const float* gb = g_WSC + (size_t)s2 * STAGE_F + t * 4;
            cp16(sb, gb);
            cp16(sb + 4096, gb + 1024);
        }
        cp_commit();

        const int v = s >> 2;
        const float zr0 = zsh[ln0][v];
        const float zr1 = zsh[ln0 + 1][v];
        const ulonglong2* Wb = (const ulonglong2*)(Wsm + b * STAGE_F);
        const int ub = (s & 3) * 16;

#pragma unroll
        for (int ui = 0; ui < 16; ui++) {
            int u = ub + ui;
            float4 xq0 = Xs[u * 32 + ln0];
            float4 xq1 = Xs[u * 32 + ln0 + 1];
            ulonglong2 wl20 = Wb[(0 * 16 + ui) * 16 + w4];
            ulonglong2 wl21 = Wb[(1 * 16 + ui) * 16 + w4];

            u64t a00 = pack2s(xq0.x * zr0), a01 = pack2s(xq0.y * zr0);
            u64t a02 = pack2s(xq0.z * zr0), a03 = pack2s(xq0.w * zr0);
            u64t a10 = pack2s(xq1.x * zr1), a11 = pack2s(xq1.y * zr1);
            u64t a12 = pack2s(xq1.z * zr1), a13 = pack2s(xq1.w * zr1);

            ffma2(acc2[0],  a00, wl20.x); ffma2(acc2[1],  a00, wl20.y);
            ffma2(acc2[2],  a01, wl21.x); ffma2(acc2[3],  a01, wl21.y);
            ffma2(acc2[4],  a02, wl21.x); ffma2(acc2[5],  a02, wl21.y);
            ffma2(acc2[6],  a03, wl21.x); ffma2(acc2[7],  a03, wl21.y);
            ffma2(acc2[8],  a10, wl20.x); ffma2(acc2[9],  a10, wl20.y);
            ffma2(acc2[10], a11, wl21.x); ffma2(acc2[11], a11, wl21.y);
            ffma2(acc2[12], a12, wl21.x); ffma2(acc2[13], a12, wl21.y);
            ffma2(acc2[14], a13, wl21.x); ffma2(acc2[15], a13, wl21.y);
        }

        if (++b >= 3) b -= 3;
    }

    float acc[32];
#pragma unroll
    for (int p = 0; p < 16; p++) unpack2(acc2[p], acc[2 * p], acc[2 * p + 1]);

    const float sc = 0.03952847075210474f * 0.1f;
#pragma unroll
    for (int nn2 = 0; nn2 < 2; nn2++) {
        int node = nbase + ln0 + nn2;
        if (node >= n) continue;
        float* os = out + (size_t)node * FEAT;
        const float* a = acc + nn2 * 16;
#pragma unroll
        for (int j = 0; j < 4; j++) {
            int w = w4 * 4 + j;
            os[w] += a[j] * sc;
#pragma unroll
            for (int c = 1; c < 4; c++)
                os[64 + 3 * w + c - 1] += a[c * 4 + j] * sc;
        }
    }
}

// ---------------- edge kernel (planar xl) ----------------
#define EPW 4
__global__ __launch_bounds__(256) void edge_kernel(
    const int* __restrict__ esrc, const int* __restrict__ edst,
    const float* __restrict__ elen, const float* __restrict__ eattr,
    int n_edges)
{
    const int warp = threadIdx.x >> 5;
    const int lane = threadIdx.x & 31;
    const int ebase = (blockIdx.x * 8 + warp) * EPW;
    if (ebase >= n_edges) return;

    float el[EPW];
    int esafe[EPW];
    bool valid[EPW];
#pragma unroll
    for (int j = 0; j < EPW; j++) {
        int e = ebase + j;
        valid[j] = (e < n_edges);
        esafe[j] = valid[j] ? e : (n_edges - 1);
        el[j] = elen[(size_t)esafe[j] * 32 + lane];
    }

    u64t acc2[EPW * 4];
#pragma unroll
    for (int i = 0; i < EPW * 4; i++) acc2[i] = 0ull;
    const ulonglong2* tpA8 = (const ulonglong2*)g_tppA;
    const ulonglong2* tpB8 = (const ulonglong2*)g_tppB;
#pragma unroll 8
    for (int d = 0; d < 32; d++) {
        ulonglong2 tA = tpA8[d * 32 + lane];
        ulonglong2 tB = tpB8[d * 32 + lane];
#pragma unroll
        for (int j = 0; j < EPW; j++) {
            u64t ed = pack2s(__shfl_sync(0xffffffffu, el[j], d));
            ffma2(acc2[j * 4 + 0], ed, tA.x);
            ffma2(acc2[j * 4 + 1], ed, tA.y);
            ffma2(acc2[j * 4 + 2], ed, tB.x);
            ffma2(acc2[j * 4 + 3], ed, tB.y);
        }
    }

    const float ISQ2 = 0.7071067811865476f;
    const float ISQ3 = 0.5773502691896258f;

#pragma unroll
    for (int j = 0; j < EPW; j++) {
        if (!valid[j]) continue;
        int e = esafe[j];
        int src = esrc[e];
        int dst = edst[e];
        float4 at = ((const float4*)eattr)[e];

        float wv[8];
        unpack2(acc2[j * 4 + 0], wv[0], wv[1]);
        unpack2(acc2[j * 4 + 1], wv[2], wv[3]);
        unpack2(acc2[j * 4 + 2], wv[4], wv[5]);
        unpack2(acc2[j * 4 + 3], wv[6], wv[7]);

        const float* xb = g_xl + (size_t)src * 64;
        float* aggp = g_agg + (size_t)dst * FEAT;
#pragma unroll
        for (int h = 0; h < 2; h++) {
            int u = lane + 32 * h;
            float x0  = xb[u];
            float x10 = xb[1 * PLANE + u];
            float x11 = xb[2 * PLANE + u];
            float x12 = xb[3 * PLANE + u];
            float w1  = wv[h * 4 + 0];
            float w2v = wv[h * 4 + 1];
            float w3  = wv[h * 4 + 2];
            float w4v = wv[h * 4 + 3];
            float dot = x10 * at.y + x11 * at.z + x12 * at.w;
            float4 o;
            o.x = ISQ2 * (w1 * x0 * at.x + ISQ3 * w4v * dot);
            o.y = ISQ2 * (w2v * x0 * at.y + w3 * x10 * at.x);
            o.z = ISQ2 * (w2v * x0 * at.z + w3 * x11 * at.x);
            o.w = ISQ2 * (w2v * x0 * at.w + w3 * x12 * at.x);
            red_add_v4(aggp + u * 4, o);
        }
    }
}

// ---------------- launch ----------------
extern "C" void kernel_launch(void* const* d_in, const int* in_sizes, int n_in,
                              void* d_out, int out_size) {
    const float* x     = (const float*)d_in[0];
    const float* z     = (const float*)d_in[1];
    const int*   esrc  = (const int*)d_in[2];
    const int*   edst  = (const int*)d_in[3];
    const float* elen  = (const float*)d_in[4];
    const float* eattr = (const float*)d_in[5];
    const float* Wsi0  = (const float*)d_in[6];
    const float* Wsi1  = (const float*)d_in[7];
    const float* Wl10  = (const float*)d_in[8];
    const float* Wl11  = (const float*)d_in[9];
    const float* Wl20  = (const float*)d_in[10];
    const float* Wl21  = (const float*)d_in[11];
    const float* tpw   = (const float*)d_in[12];
    float* out = (float*)d_out;

    const int n_nodes = in_sizes[0] / FEAT;
    const int n_edges = in_sizes[2];

    cudaFuncSetAttribute(fctp_dual_mma_kernel,
                         cudaFuncAttributeMaxDynamicSharedMemorySize, SMEM_NEED);

    prepack_wf_kernel<<<(40 * 4 * 16 * 32 + 255) / 256, 256>>>(Wsi0, Wsi1, Wl10, Wl11);
    prepack_final_kernel<<<(64 * 10 * 64 + 255) / 256, 256>>>(Wl20, Wl21);
    prepack_tp_kernel<<<4, 256>>>(tpw);
    zero_agg_kernel<<<512, 256>>>(n_nodes * (FEAT / 4));

    const int ntiles = (n_nodes + 127) / 128;
    fctp_dual_mma_kernel<<<ntiles, 256, SMEM_NEED>>>(x, z, out, n_nodes);

    const int edges_per_block = 8 * EPW;
    edge_kernel<<<(n_edges + edges_per_block - 1) / edges_per_block, 256>>>(
        esrc, edst, elen, eattr, n_edges);

    const int nblocks = (n_nodes + 31) / 32;
    fctp_final_kernel<<<nblocks, 256>>>(z, out, n_nodes);
}

// round 12
// speedup vs baseline: 1.7592x; 1.1874x over previous
#include <cuda_runtime.h>
#include <cuda_bf16.h>
#include <cstdint>

#define N_NODES_MAX 50016
#define FEAT 256
#define PLANE (N_NODES_MAX * 64)

typedef unsigned long long u64t;

// ---------------- scratch ----------------
__device__ float g_xl[4 * PLANE];             // planar: plane c, [node][u]
__device__ float g_agg[N_NODES_MAX * FEAT];   // quad layout [node][u][4]
// Fragment-linear B weights for dual MMA (N=128):
// idx = ((s*4 + kc)*16 + nt)*32 + lane ; uint4 = {BhR0, BhR1, BlR0, BlR1}
__device__ uint4 g_WF[40 * 4 * 16 * 32];
// Fragment-linear B weights for final MMA (N=64):
// idx = ((s*4 + kc)*8 + nt)*32 + lane
__device__ uint4 g_WF2[40 * 4 * 8 * 32];
__device__ float g_tppA[32 * 32 * 4];
__device__ float g_tppB[32 * 32 * 4];

// ---------------- helpers ----------------
__device__ __forceinline__ u64t pack2s(float a) {
    u64t r; asm("mov.b64 %0, {%1, %1};" : "=l"(r) : "f"(a)); return r;
}
__device__ __forceinline__ void unpack2(u64t v, float& a, float& b) {
    asm("mov.b64 {%0, %1}, %2;" : "=f"(a), "=f"(b) : "l"(v));
}
__device__ __forceinline__ void ffma2(u64t& d, u64t a, u64t b) {
    asm("fma.rn.f32x2 %0, %1, %2, %0;" : "+l"(d) : "l"(a), "l"(b));
}
__device__ __forceinline__ void red_add_v4(float* p, float4 v) {
    asm volatile("red.global.add.v4.f32 [%0], {%1,%2,%3,%4};"
                 :: "l"(p), "f"(v.x), "f"(v.y), "f"(v.z), "f"(v.w) : "memory");
}
__device__ __forceinline__ void cp16(uint32_t saddr, const void* g) {
    asm volatile("cp.async.cg.shared.global [%0], [%1], 16;" :: "r"(saddr), "l"(g));
}
__device__ __forceinline__ void cp_commit() { asm volatile("cp.async.commit_group;" ::: "memory"); }
__device__ __forceinline__ void cp_waitg1() { asm volatile("cp.async.wait_group 1;" ::: "memory"); }
__device__ __forceinline__ uint32_t smem_u32(const void* p) {
    uint32_t a;
    asm("{ .reg .u64 t; cvta.to.shared.u64 t, %1; cvt.u32.u64 %0, t; }" : "=r"(a) : "l"(p));
    return a;
}
// split a pair of f32 into packed bf16x2 hi and lo parts: {lo16 = e0, hi16 = e1}
__device__ __forceinline__ void split2(float e0, float e1, uint32_t& hp, uint32_t& lp) {
    asm("cvt.rn.bf16x2.f32 %0, %1, %2;" : "=r"(hp) : "f"(e1), "f"(e0));
    float h0 = __uint_as_float(hp << 16);
    float h1 = __uint_as_float(hp & 0xFFFF0000u);
    asm("cvt.rn.bf16x2.f32 %0, %1, %2;" : "=r"(lp) : "f"(e1 - h1), "f"(e0 - h0));
}

#define MMA16816(c, a, b0, b1) \
    asm volatile("mma.sync.aligned.m16n8k16.row.col.f32.bf16.bf16.f32 " \
        "{%0,%1,%2,%3}, {%4,%5,%6,%7}, {%8,%9}, {%0,%1,%2,%3};" \
        : "+f"((c)[0]), "+f"((c)[1]), "+f"((c)[2]), "+f"((c)[3]) \
        : "r"((a)[0]), "r"((a)[1]), "r"((a)[2]), "r"((a)[3]), "r"(b0), "r"(b1))

// ---------------- prepacks ----------------
__global__ void prepack_wf_kernel(const float* __restrict__ si0, const float* __restrict__ si1,
                                  const float* __restrict__ l10, const float* __restrict__ l11) {
    int idx = blockIdx.x * blockDim.x + threadIdx.x;
    if (idx >= 40 * 4 * 16 * 32) return;
    int lane = idx & 31;
    int nt = (idx >> 5) & 15;
    int kc = (idx >> 9) & 3;
    int s = idx >> 11;
    int ch = s / 10, v = s % 10;
    int gid = lane >> 2, t2 = lane & 3;
    int n = nt * 8 + gid;
    int w = n & 63;
    const float* src = (n >= 64) ? (ch == 0 ? l10 : l11) : (ch == 0 ? si0 : si1);
    int u0 = kc * 16 + t2 * 2;
    float v00 = src[((u0 + 0) * 10 + v) * 64 + w];
    float v01 = src[((u0 + 1) * 10 + v) * 64 + w];
    float v10 = src[((u0 + 8) * 10 + v) * 64 + w];
    float v11 = src[((u0 + 9) * 10 + v) * 64 + w];
    uint32_t h0, l0, h1, l1;
    split2(v00, v01, h0, l0);
    split2(v10, v11, h1, l1);
    g_WF[idx] = make_uint4(h0, h1, l0, l1);
}

__global__ void prepack_wf2_kernel(const float* __restrict__ l20, const float* __restrict__ l21) {
    int idx = blockIdx.x * blockDim.x + threadIdx.x;
    if (idx >= 40 * 4 * 8 * 32) return;
    int lane = idx & 31;
    int nt = (idx >> 5) & 7;
    int kc = (idx >> 8) & 3;
    int s = idx >> 10;
    int ch = s / 10, v = s % 10;
    int gid = lane >> 2, t2 = lane & 3;
    int w = nt * 8 + gid;      // 0..63
    const float* src = (ch == 0) ? l20 : l21;
    int u0 = kc * 16 + t2 * 2;
    float v00 = src[((u0 + 0) * 10 + v) * 64 + w];
    float v01 = src[((u0 + 1) * 10 + v) * 64 + w];
    float v10 = src[((u0 + 8) * 10 + v) * 64 + w];
    float v11 = src[((u0 + 9) * 10 + v) * 64 + w];
    uint32_t h0, l0, h1, l1;
    split2(v00, v01, h0, l0);
    split2(v10, v11, h1, l1);
    g_WF2[idx] = make_uint4(h0, h1, l0, l1);
}

__global__ void prepack_tp_kernel(const float* __restrict__ tpw) {
    int i = blockIdx.x * blockDim.x + threadIdx.x;
    if (i >= 32 * 32) return;
    int d = i >> 5, lane = i & 31;
    const float* row = tpw + d * 256;
    float* a = g_tppA + i * 4;
    a[0] = row[lane];        a[1] = row[64 + lane];
    a[2] = row[128 + lane];  a[3] = row[192 + lane];
    float* b = g_tppB + i * 4;
    b[0] = row[32 + lane];   b[1] = row[96 + lane];
    b[2] = row[160 + lane];  b[3] = row[224 + lane];
}

__global__ void zero_agg_kernel(int n4) {
    float4* p = (float4*)g_agg;
    float4 z = make_float4(0.f, 0.f, 0.f, 0.f);
    for (int i = blockIdx.x * blockDim.x + threadIdx.x; i < n4; i += gridDim.x * blockDim.x)
        p[i] = z;
}

// ---------------- fctp dual via mma.sync (unchanged from R11) ----------------
#define OFF_XS 65536
#define OFF_ZS (65536 + 34816)
#define SMEM_NEED (65536 + 34816 + 5120)

__global__ __launch_bounds__(256, 2) void fctp_dual_mma_kernel(
    const float* __restrict__ x, const float* __restrict__ z,
    float* __restrict__ out_s, int nn)
{
    extern __shared__ char sm[];
    char* Bsm = sm;
    float* xs = (float*)(sm + OFF_XS);
    float* zs = (float*)(sm + OFF_ZS);

    const int t = threadIdx.x;
    const int wid = t >> 5;
    const int lane = t & 31;
    const int gid = lane >> 2;
    const int t2 = lane & 3;
    const int warp_m = wid & 3;
    const int warp_n = wid >> 2;
    const int nbase = blockIdx.x * 128;

    const uint32_t bsm_u = smem_u32(Bsm);

    for (int i = t; i < 1280; i += 256) {
        int node = nbase + i / 10;
        zs[i] = (node < nn) ? z[(size_t)nbase * 10 + i] : 0.f;
    }
    {
        const uint4* gsrc = g_WF;
#pragma unroll
        for (int k = 0; k < 8; k++)
            cp16(bsm_u + t * 16 + k * 4096, gsrc + t + k * 256);
        cp_commit();
    }

    float acc[2][8][4];
#pragma unroll
    for (int a = 0; a < 2; a++)
#pragma unroll
        for (int b = 0; b < 8; b++)
#pragma unroll
            for (int c = 0; c < 4; c++) acc[a][b][c] = 0.f;

    const float sc = 0.03952847075210474f;

    for (int s = 0; s < 40; s++) {
        const int ch = s / 10;
        const int v = s % 10;
        const int buf = s & 1;

        __syncthreads();

        if (v == 0) {
            for (int i = t; i < 8192; i += 256) {
                int row = i >> 6, u = i & 63;
                int node = nbase + row;
                int col = (ch == 0) ? u : (64 + 3 * u + (ch - 1));
                xs[row * 68 + u] = (node < nn) ? x[(size_t)node * 256 + col] : 0.f;
            }
        }
        if (s + 1 < 40) {
            const uint4* gsrc = g_WF + (size_t)(s + 1) * 2048;
            uint32_t dst = bsm_u + (buf ^ 1) * 32768;
#pragma unroll
            for (int k = 0; k < 8; k++)
                cp16(dst + t * 16 + k * 4096, gsrc + t + k * 256);
        }
        cp_commit();
        cp_waitg1();
        __syncthreads();

        float zr[2][2];
#pragma unroll
        for (int mt = 0; mt < 2; mt++) {
            int r = warp_m * 32 + mt * 16 + gid;
            zr[mt][0] = zs[r * 10 + v];
            zr[mt][1] = zs[(r + 8) * 10 + v];
        }

        char* Bbuf = Bsm + buf * 32768;

#pragma unroll 1
        for (int kc = 0; kc < 4; kc++) {
            uint32_t Ah[2][4], Al[2][4];
#pragma unroll
            for (int mt = 0; mt < 2; mt++) {
                int r0 = warp_m * 32 + mt * 16 + gid;
                int ub = kc * 16 + t2 * 2;
                float2 x00 = *(const float2*)(xs + r0 * 68 + ub);
                float2 x01 = *(const float2*)(xs + r0 * 68 + ub + 8);
                float2 x10 = *(const float2*)(xs + (r0 + 8) * 68 + ub);
                float2 x11 = *(const float2*)(xs + (r0 + 8) * 68 + ub + 8);
                float z0 = zr[mt][0], z1 = zr[mt][1];
                split2(x00.x * z0, x00.y * z0, Ah[mt][0], Al[mt][0]);
                split2(x10.x * z1, x10.y * z1, Ah[mt][1], Al[mt][1]);
                split2(x01.x * z0, x01.y * z0, Ah[mt][2], Al[mt][2]);
                split2(x11.x * z1, x11.y * z1, Ah[mt][3], Al[mt][3]);
            }
#pragma unroll
            for (int nt = 0; nt < 8; nt++) {
                uint4 B4 = *(const uint4*)(Bbuf + (((kc * 16) + warp_n * 8 + nt) * 32 + lane) * 16);
#pragma unroll
                for (int mt = 0; mt < 2; mt++) {
                    MMA16816(acc[mt][nt], Ah[mt], B4.x, B4.y);
                    MMA16816(acc[mt][nt], Ah[mt], B4.z, B4.w);
                    MMA16816(acc[mt][nt], Al[mt], B4.x, B4.y);
                }
            }
        }

        if (v == 9) {
#pragma unroll
            for (int mt = 0; mt < 2; mt++) {
#pragma unroll
                for (int nt = 0; nt < 8; nt++) {
                    int ntg = warp_n * 8 + nt;
                    int n0 = ntg * 8 + t2 * 2;
                    int r0 = nbase + warp_m * 32 + mt * 16 + gid;
                    int r1 = r0 + 8;
                    float c0 = acc[mt][nt][0] * sc;
                    float c1 = acc[mt][nt][1] * sc;
                    float c2 = acc[mt][nt][2] * sc;
                    float c3 = acc[mt][nt][3] * sc;
                    if (warp_n == 0) {
                        int w = n0;
                        if (ch == 0) {
                            if (r0 < nn) *(float2*)(out_s + (size_t)r0 * 256 + w) = make_float2(c0, c1);
                            if (r1 < nn) *(float2*)(out_s + (size_t)r1 * 256 + w) = make_float2(c2, c3);
                        } else {
                            int off = 64 + 3 * w + (ch - 1);
                            if (r0 < nn) {
                                out_s[(size_t)r0 * 256 + off] = c0;
                                out_s[(size_t)r0 * 256 + off + 3] = c1;
                            }
                            if (r1 < nn) {
                                out_s[(size_t)r1 * 256 + off] = c2;
                                out_s[(size_t)r1 * 256 + off + 3] = c3;
                            }
                        }
                    } else {
                        int w = n0 - 64;
                        float* xlp = g_xl + (size_t)ch * PLANE;
                        if (r0 < nn) *(float2*)(xlp + (size_t)r0 * 64 + w) = make_float2(c0, c1);
                        if (r1 < nn) *(float2*)(xlp + (size_t)r1 * 64 + w) = make_float2(c2, c3);
                    }
                    acc[mt][nt][0] = 0.f; acc[mt][nt][1] = 0.f;
                    acc[mt][nt][2] = 0.f; acc[mt][nt][3] = 0.f;
                }
            }
        }
    }
}

// ---------------- fctp final via mma.sync (N=64) ----------------
// smem: Bsm 2x16384 | xs 128x68 f32 (34816 B) | zs 1280 f32
#define F_OFF_XS 32768
#define F_OFF_ZS (32768 + 34816)
#define F_SMEM_NEED (32768 + 34816 + 5120)

__global__ __launch_bounds__(256, 2) void fctp_final_mma_kernel(
    const float* __restrict__ z, float* __restrict__ out, int nn)
{
    extern __shared__ char sm[];
    char* Bsm = sm;
    float* xs = (float*)(sm + F_OFF_XS);
    float* zs = (float*)(sm + F_OFF_ZS);

    const int t = threadIdx.x;
    const int wid = t >> 5;      // warp_m = wid (8 m-tiles x 16 rows)
    const int lane = t & 31;
    const int gid = lane >> 2;
    const int t2 = lane & 3;
    const int nbase = blockIdx.x * 128;

    const uint32_t bsm_u = smem_u32(Bsm);

    for (int i = t; i < 1280; i += 256) {
        int node = nbase + i / 10;
        zs[i] = (node < nn) ? z[(size_t)nbase * 10 + i] : 0.f;
    }
    {
        const uint4* gsrc = g_WF2;
#pragma unroll
        for (int k = 0; k < 4; k++)
            cp16(bsm_u + t * 16 + k * 4096, gsrc + t + k * 256);
        cp_commit();
    }

    float acc[8][4];
#pragma unroll
    for (int b = 0; b < 8; b++)
#pragma unroll
        for (int c = 0; c < 4; c++) acc[b][c] = 0.f;

    const float sc = 0.03952847075210474f * 0.1f;  // (1/sqrt(640))/10
    const float4* agg4 = (const float4*)g_agg;

    for (int s = 0; s < 40; s++) {
        const int ch = s / 10;
        const int v = s % 10;
        const int buf = s & 1;

        __syncthreads();

        if (v == 0) {
            // stage channel slice of agg (quad -> plane)
            for (int i = t; i < 8192; i += 256) {
                int row = i >> 6, u = i & 63;
                int node = nbase + row;
                float val = 0.f;
                if (node < nn) {
                    float4 q = agg4[(size_t)node * 64 + u];
                    val = (ch == 0) ? q.x : (ch == 1) ? q.y : (ch == 2) ? q.z : q.w;
                }
                xs[row * 68 + u] = val;
            }
        }
        if (s + 1 < 40) {
            const uint4* gsrc = g_WF2 + (size_t)(s + 1) * 1024;
            uint32_t dst = bsm_u + (buf ^ 1) * 16384;
#pragma unroll
            for (int k = 0; k < 4; k++)
                cp16(dst + t * 16 + k * 4096, gsrc + t + k * 256);
        }
        cp_commit();
        cp_waitg1();
        __syncthreads();

        int r0g = wid * 16 + gid;
        float z0 = zs[r0g * 10 + v];
        float z1 = zs[(r0g + 8) * 10 + v];

        char* Bbuf = Bsm + buf * 16384;

#pragma unroll 1
        for (int kc = 0; kc < 4; kc++) {
            uint32_t Ah[4], Al[4];
            {
                int ub = kc * 16 + t2 * 2;
                float2 x00 = *(const float2*)(xs + r0g * 68 + ub);
                float2 x01 = *(const float2*)(xs + r0g * 68 + ub + 8);
                float2 x10 = *(const float2*)(xs + (r0g + 8) * 68 + ub);
                float2 x11 = *(const float2*)(xs + (r0g + 8) * 68 + ub + 8);
                split2(x00.x * z0, x00.y * z0, Ah[0], Al[0]);
                split2(x10.x * z1, x10.y * z1, Ah[1], Al[1]);
                split2(x01.x * z0, x01.y * z0, Ah[2], Al[2]);
                split2(x11.x * z1, x11.y * z1, Ah[3], Al[3]);
            }
#pragma unroll
            for (int nt = 0; nt < 8; nt++) {
                uint4 B4 = *(const uint4*)(Bbuf + ((kc * 8 + nt) * 32 + lane) * 16);
                MMA16816(acc[nt], Ah, B4.x, B4.y);
                MMA16816(acc[nt], Ah, B4.z, B4.w);
                MMA16816(acc[nt], Al, B4.x, B4.y);
            }
        }

        if (v == 9) {
            // epilogue: out += acc * sc
#pragma unroll
            for (int nt = 0; nt < 8; nt++) {
                int w = nt * 8 + t2 * 2;
                int r0 = nbase + wid * 16 + gid;
                int r1 = r0 + 8;
                float c0 = acc[nt][0] * sc;
                float c1 = acc[nt][1] * sc;
                float c2 = acc[nt][2] * sc;
                float c3 = acc[nt][3] * sc;
                if (ch == 0) {
                    if (r0 < nn) {
                        float2* p = (float2*)(out + (size_t)r0 * 256 + w);
                        float2 o = *p; o.x += c0; o.y += c1; *p = o;
                    }
                    if (r1 < nn) {
                        float2* p = (float2*)(out + (size_t)r1 * 256 + w);
                        float2 o = *p; o.x += c2; o.y += c3; *p = o;
                    }
                } else {
                    int off = 64 + 3 * w + (ch - 1);
                    if (r0 < nn) {
                        out[(size_t)r0 * 256 + off] += c0;
                        out[(size_t)r0 * 256 + off + 3] += c1;
                    }
                    if (r1 < nn) {
                        out[(size_t)r1 * 256 + off] += c2;
                        out[(size_t)r1 * 256 + off + 3] += c3;
                    }
                }
                acc[nt][0] = 0.f; acc[nt][1] = 0.f;
                acc[nt][2] = 0.f; acc[nt][3] = 0.f;
            }
        }
    }
}

// ---------------- edge kernel (planar xl) ----------------
#define EPW 4
__global__ __launch_bounds__(256) void edge_kernel(
    const int* __restrict__ esrc, const int* __restrict__ edst,
    const float* __restrict__ elen, const float* __restrict__ eattr,
    int n_edges)
{
    const int warp = threadIdx.x >> 5;
    const int lane = threadIdx.x & 31;
    const int ebase = (blockIdx.x * 8 + warp) * EPW;
    if (ebase >= n_edges) return;

    float el[EPW];
    int esafe[EPW];
    bool valid[EPW];
#pragma unroll
    for (int j = 0; j < EPW; j++) {
        int e = ebase + j;
        valid[j] = (e < n_edges);
        esafe[j] = valid[j] ? e : (n_edges - 1);
        el[j] = elen[(size_t)esafe[j] * 32 + lane];
    }

    u64t acc2[EPW * 4];
#pragma unroll
    for (int i = 0; i < EPW * 4; i++) acc2[i] = 0ull;
    const ulonglong2* tpA8 = (const ulonglong2*)g_tppA;
    const ulonglong2* tpB8 = (const ulonglong2*)g_tppB;
#pragma unroll 8
    for (int d = 0; d < 32; d++) {
        ulonglong2 tA = tpA8[d * 32 + lane];
        ulonglong2 tB = tpB8[d * 32 + lane];
#pragma unroll
        for (int j = 0; j < EPW; j++) {
            u64t ed = pack2s(__shfl_sync(0xffffffffu, el[j], d));
            ffma2(acc2[j * 4 + 0], ed, tA.x);
            ffma2(acc2[j * 4 + 1], ed, tA.y);
            ffma2(acc2[j * 4 + 2], ed, tB.x);
            ffma2(acc2[j * 4 + 3], ed, tB.y);
        }
    }

    const float ISQ2 = 0.7071067811865476f;
    const float ISQ3 = 0.5773502691896258f;

#pragma unroll
    for (int j = 0; j < EPW; j++) {
        if (!valid[j]) continue;
        int e = esafe[j];
        int src = esrc[e];
        int dst = edst[e];
        float4 at = ((const float4*)eattr)[e];

        float wv[8];
        unpack2(acc2[j * 4 + 0], wv[0], wv[1]);
        unpack2(acc2[j * 4 + 1], wv[2], wv[3]);
        unpack2(acc2[j * 4 + 2], wv[4], wv[5]);
        unpack2(acc2[j * 4 + 3], wv[6], wv[7]);

        const float* xb = g_xl + (size_t)src * 64;
        float* aggp = g_agg + (size_t)dst * FEAT;
#pragma unroll
        for (int h = 0; h < 2; h++) {
            int u = lane + 32 * h;
            float x0  = xb[u];
            float x10 = xb[1 * PLANE + u];
            float x11 = xb[2 * PLANE + u];
            float x12 = xb[3 * PLANE + u];
            float w1  = wv[h * 4 + 0];
            float w2v = wv[h * 4 + 1];
            float w3  = wv[h * 4 + 2];
            float w4v = wv[h * 4 + 3];
            float dot = x10 * at.y + x11 * at.z + x12 * at.w;
            float4 o;
            o.x = ISQ2 * (w1 * x0 * at.x + ISQ3 * w4v * dot);
            o.y = ISQ2 * (w2v * x0 * at.y + w3 * x10 * at.x);
            o.z = ISQ2 * (w2v * x0 * at.z + w3 * x11 * at.x);
            o.w = ISQ2 * (w2v * x0 * at.w + w3 * x12 * at.x);
            red_add_v4(aggp + u * 4, o);
        }
    }
}

// ---------------- launch ----------------
extern "C" void kernel_launch(void* const* d_in, const int* in_sizes, int n_in,
                              void* d_out, int out_size) {
    const float* x     = (const float*)d_in[0];
    const float* z     = (const float*)d_in[1];
    const int*   esrc  = (const int*)d_in[2];
    const int*   edst  = (const int*)d_in[3];
    const float* elen  = (const float*)d_in[4];
    const float* eattr = (const float*)d_in[5];
    const float* Wsi0  = (const float*)d_in[6];
    const float* Wsi1  = (const float*)d_in[7];
    const float* Wl10  = (const float*)d_in[8];
    const float* Wl11  = (const float*)d_in[9];
    const float* Wl20  = (const float*)d_in[10];
    const float* Wl21  = (const float*)d_in[11];
    const float* tpw   = (const float*)d_in[12];
    float* out = (float*)d_out;

    const int n_nodes = in_sizes[0] / FEAT;
    const int n_edges = in_sizes[2];

    cudaFuncSetAttribute(fctp_dual_mma_kernel,
                         cudaFuncAttributeMaxDynamicSharedMemorySize, SMEM_NEED);
    cudaFuncSetAttribute(fctp_final_mma_kernel,
                         cudaFuncAttributeMaxDynamicSharedMemorySize, F_SMEM_NEED);

    prepack_wf_kernel<<<(40 * 4 * 16 * 32 + 255) / 256, 256>>>(Wsi0, Wsi1, Wl10, Wl11);
    prepack_wf2_kernel<<<(40 * 4 * 8 * 32 + 255) / 256, 256>>>(Wl20, Wl21);
    prepack_tp_kernel<<<4, 256>>>(tpw);
    zero_agg_kernel<<<512, 256>>>(n_nodes * (FEAT / 4));

    const int ntiles = (n_nodes + 127) / 128;
    fctp_dual_mma_kernel<<<ntiles, 256, SMEM_NEED>>>(x, z, out, n_nodes);

    const int edges_per_block = 8 * EPW;
    edge_kernel<<<(n_edges + edges_per_block - 1) / edges_per_block, 256>>>(
        esrc, edst, elen, eattr, n_edges);

    fctp_final_mma_kernel<<<ntiles, 256, F_SMEM_NEED>>>(z, out, n_nodes);
}